// round 13
// baseline (speedup 1.0000x reference)
#include <cuda_runtime.h>
#include <cstdint>

#define N_    2
#define CIN   32
#define T_    8
#define H_    56
#define W_    56
#define COUT  64
#define KVOL  27
#define SP    25088   // T*H*W
#define HW    3136    // H*W
#define CROW  36      // col row stride: [pos][c], padded 32->36 (B-frag conflict-free)

// Scratch (no allocations allowed in kernel_launch)
__device__ float    g_xt[(size_t)N_ * SP * CIN];   // x -> [N, T*H*W, C]
__device__ uint32_t g_wfrag[KVOL * 2048];          // w -> [k][fragword(16)][c4*32+lane], tf32

__device__ __forceinline__ uint32_t f2tf32(float f) {
    uint32_t r; asm("cvt.rna.tf32.f32 %0, %1;" : "=r"(r) : "f"(f));
    return r;
}

// ---------------------------------------------------------------------------
// Merged prep: blocks [0,1568) transpose x; blocks [1568,1784) build w frags.
// ---------------------------------------------------------------------------
__global__ __launch_bounds__(256) void prep(const float* __restrict__ x,
                                            const float* __restrict__ w) {
    __shared__ float sm[32][33];
    int bx = blockIdx.x;
    if (bx < 1568) {
        int n  = bx >= 784 ? 1 : 0;
        int sb = bx - n * 784;
        int s0 = sb * 32;
        int tx = threadIdx.x & 31;
        int ty = threadIdx.x >> 5;
#pragma unroll
        for (int r = 0; r < 4; ++r) {
            int c = ty + r * 8;
            sm[c][tx] = x[((size_t)n * CIN + c) * SP + s0 + tx];
        }
        __syncthreads();
#pragma unroll
        for (int r = 0; r < 4; ++r) {
            int j = ty + r * 8;
            g_xt[((size_t)n * SP + s0 + j) * CIN + tx] = sm[tx][j];
        }
    } else {
        // fragment-ordered weights for mma.m16n8k8 (A row-major = [co][c])
        int i = (bx - 1568) * 256 + threadIdx.x;   // 0 .. 55295 = 27*2048
        int k  = i >> 11;
        int r  = i & 2047;
        int wd = r >> 7;
        int t  = r & 127;
        int c4 = t >> 5;
        int ln = t & 31;
        int g  = ln >> 2, tg = ln & 3;
        int kk = wd >> 2, rr = wd & 3;
        int co = c4 * 16 + g + (rr & 1) * 8;
        int c  = kk * 8 + tg + (rr >> 1) * 4;
        g_wfrag[i] = f2tf32(w[((size_t)co * CIN + c) * KVOL + k]);
    }
}

// ---------------------------------------------------------------------------
// Compute one tap's 32 sampling records into smem (warp 0 only).
// Record = 8 corner weights + 8 pre-shifted indices, 16 words, 64 B.
// ---------------------------------------------------------------------------
__device__ __forceinline__ void make_rec(
    int k, int n, int s, float bt, float bh, float bw,
    const float* __restrict__ offset, float* __restrict__ rec /* [16] */)
{
    int kt = k / 9;
    int r9 = k - kt * 9;
    int kh = r9 / 3;
    int kw = r9 - kh * 3;

    const float* ob = offset + ((size_t)n * 81 + k * 3) * SP + s;   // coalesced in s
    float pt = bt + (float)kt + ob[0];
    float ph = bh + (float)kh + ob[SP];
    float pw = bw + (float)kw + ob[2 * (size_t)SP];

    float tf = floorf(pt), hf = floorf(ph), wf = floorf(pw);
    int t0 = (int)tf, h0 = (int)hf, w0 = (int)wf;
    float lt = pt - tf, lh = ph - hf, lw = pw - wf;

    float wt0 = (t0 >= 0 && t0 < T_)         ? 1.f - lt : 0.f;
    float wt1 = (t0 + 1 >= 0 && t0 + 1 < T_) ? lt       : 0.f;
    float wh0 = (h0 >= 0 && h0 < H_)         ? 1.f - lh : 0.f;
    float wh1 = (h0 + 1 >= 0 && h0 + 1 < H_) ? lh       : 0.f;
    float ww0 = (w0 >= 0 && w0 < W_)         ? 1.f - lw : 0.f;
    float ww1 = (w0 + 1 >= 0 && w0 + 1 < W_) ? lw       : 0.f;

    int t0c = min(max(t0, 0), T_ - 1), t1c = min(max(t0 + 1, 0), T_ - 1);
    int h0c = min(max(h0, 0), H_ - 1), h1c = min(max(h0 + 1, 0), H_ - 1);
    int w0c = min(max(w0, 0), W_ - 1), w1c = min(max(w0 + 1, 0), W_ - 1);

    int i00 = (t0c * H_ + h0c) * W_;
    int i01 = (t0c * H_ + h1c) * W_;
    int i10 = (t1c * H_ + h0c) * W_;
    int i11 = (t1c * H_ + h1c) * W_;

    float m00 = wt0 * wh0, m01 = wt0 * wh1, m10 = wt1 * wh0, m11 = wt1 * wh1;
    float4* rp = (float4*)rec;
    rp[0] = make_float4(m00 * ww0, m00 * ww1, m01 * ww0, m01 * ww1);
    rp[1] = make_float4(m10 * ww0, m10 * ww1, m11 * ww0, m11 * ww1);
    ((int4*)rp)[2] = make_int4((i00 + w0c) << 5, (i00 + w1c) << 5,
                               (i01 + w0c) << 5, (i01 + w1c) << 5);
    ((int4*)rp)[3] = make_int4((i10 + w0c) << 5, (i10 + w1c) << 5,
                               (i11 + w0c) << 5, (i11 + w1c) << 5);
}

// ---------------------------------------------------------------------------
// Gather one tap into col buffer using smem records.
// lane = channel; each warp handles 8 positions.
// ---------------------------------------------------------------------------
__device__ __forceinline__ void gather_tap(
    const float* __restrict__ rsm, const float* __restrict__ xb,
    int lane, int warpId, float* __restrict__ col)
{
    const float* b = xb + lane;
#pragma unroll
    for (int pp = 0; pp < 8; ++pp) {
        int q = warpId * 8 + pp;
        const float4* rp = (const float4*)(rsm + q * 16);
        float4 wa = rp[0];
        float4 wb = rp[1];
        int4   ia = ((const int4*)rp)[2];
        int4   ib = ((const int4*)rp)[3];
        float val;
        val  = wa.x * b[ia.x];
        val += wa.y * b[ia.y];
        val += wa.z * b[ia.z];
        val += wa.w * b[ia.w];
        val += wb.x * b[ib.x];
        val += wb.y * b[ib.y];
        val += wb.z * b[ib.z];
        val += wb.w * b[ib.w];
        col[q * CROW + lane] = __uint_as_float(f2tf32(val));
    }
}

// ---------------------------------------------------------------------------
// Main kernel: block = 32 positions x 64 couts, 128 threads, 10 blocks/SM.
// Pipeline, ONE barrier per tap: [rec(k+2) warp0 ; gather(k+1) ; mma(k)].
// Each warp gathers 8 positions; mma: warp = co 16-band x all 32 positions.
// ---------------------------------------------------------------------------
__global__ __launch_bounds__(128, 10) void deform_conv3d_main(
    const float* __restrict__ offset,
    const float* __restrict__ bias,
    float* __restrict__ out)
{
    __shared__ __align__(16) float col[2][32 * CROW];   // 9.2 KB
    __shared__ __align__(16) float rsm[2][32 * 16];     // 4 KB records

    const int nb  = blockIdx.x;          // 0 .. 1567
    const int n   = nb >= 784 ? 1 : 0;
    const int s0  = (nb - n * 784) * 32;
    const int tid = threadIdx.x;
    const int lane   = tid & 31;
    const int warpId = tid >> 5;         // 0..3

    const int g  = lane >> 2;
    const int tg = lane & 3;
    const int cobase = warpId * 16;

    // per-thread base coords for the rec path (warp 0: one position each)
    float bt = 0.f, bh = 0.f, bw = 0.f;
    int   sMine = s0 + tid;
    if (tid < 32) {
        int to = sMine / HW;
        int rem = sMine - to * HW;
        int ho = rem / W_;
        int wo = rem - ho * W_;
        bt = (float)(to - 1);
        bh = (float)(ho - 1);
        bw = (float)(wo - 1);
    }

    float d[4][4];
#pragma unroll
    for (int j = 0; j < 4; ++j)
#pragma unroll
        for (int i = 0; i < 4; ++i) d[j][i] = 0.f;

    const float* __restrict__ xb = g_xt + (size_t)n * SP * CIN;
    const uint32_t* __restrict__ wfrag = g_wfrag + warpId * 32 + lane;

    // prologue
    if (tid < 32)
        make_rec(0, n, sMine, bt, bh, bw, offset, &rsm[0][tid * 16]);
    __syncthreads();
    gather_tap(rsm[0], xb, lane, warpId, col[0]);
    if (tid < 32)
        make_rec(1, n, sMine, bt, bh, bw, offset, &rsm[1][tid * 16]);
    __syncthreads();

#pragma unroll 1
    for (int k = 0; k < KVOL; ++k) {
        const int cur = k & 1;
        const int nxt = cur ^ 1;

        if (k + 2 < KVOL && tid < 32)
            make_rec(k + 2, n, sMine, bt, bh, bw, offset, &rsm[cur][tid * 16]);

        if (k + 1 < KVOL)
            gather_tap(rsm[nxt], xb, lane, warpId, col[nxt]);

        // ---- mma tap k: 16 x m16n8k8.tf32 per warp (co band x 32 pos) ----
        {
            const float* cb = col[cur];
            const uint32_t* wf = wfrag + k * 2048;
#pragma unroll
            for (int kk = 0; kk < 4; ++kk) {
                uint32_t a0 = wf[(kk * 4 + 0) * 128];
                uint32_t a1 = wf[(kk * 4 + 1) * 128];
                uint32_t a2 = wf[(kk * 4 + 2) * 128];
                uint32_t a3 = wf[(kk * 4 + 3) * 128];
                const int cbk = kk * 8;
#pragma unroll
                for (int j = 0; j < 4; ++j) {
                    const float* cr = cb + (8 * j + g) * CROW + cbk + tg;
                    uint32_t b0 = *(const uint32_t*)(cr);
                    uint32_t b1 = *(const uint32_t*)(cr + 4);
                    asm("mma.sync.aligned.m16n8k8.row.col.f32.tf32.tf32.f32 "
                        "{%0,%1,%2,%3}, {%4,%5,%6,%7}, {%8,%9}, {%0,%1,%2,%3};"
                        : "+f"(d[j][0]), "+f"(d[j][1]), "+f"(d[j][2]), "+f"(d[j][3])
                        : "r"(a0), "r"(a1), "r"(a2), "r"(a3), "r"(b0), "r"(b1));
                }
            }
        }
        __syncthreads();
    }

    // ---- epilogue: add bias, float2 stores ----
    float bg  = bias[cobase + g];
    float bg8 = bias[cobase + g + 8];
    float* ob0 = out + ((size_t)n * COUT + cobase + g)     * SP + s0 + 2 * tg;
    float* ob1 = out + ((size_t)n * COUT + cobase + g + 8) * SP + s0 + 2 * tg;
#pragma unroll
    for (int j = 0; j < 4; ++j) {
        *(float2*)(ob0 + 8 * j) = make_float2(d[j][0] + bg,  d[j][1] + bg);
        *(float2*)(ob1 + 8 * j) = make_float2(d[j][2] + bg8, d[j][3] + bg8);
    }
}

// ---------------------------------------------------------------------------
extern "C" void kernel_launch(void* const* d_in, const int* in_sizes, int n_in,
                              void* d_out, int out_size) {
    const float* x      = (const float*)d_in[0];
    const float* offset = (const float*)d_in[1];
    const float* weight = (const float*)d_in[2];
    const float* bias   = (const float*)d_in[3];
    float* out = (float*)d_out;

    prep<<<1784, 256>>>(x, weight);

    deform_conv3d_main<<<1568, 128>>>(offset, bias, out);
}

// round 14
// speedup vs baseline: 1.1361x; 1.1361x over previous
#include <cuda_runtime.h>
#include <cstdint>

#define N_    2
#define CIN   32
#define T_    8
#define H_    56
#define W_    56
#define COUT  64
#define KVOL  27
#define SP    25088   // T*H*W
#define HW    3136    // H*W
#define CROW  36      // col row stride: [pos][c], padded 32->36 (B-frag conflict-free)

// Scratch (no allocations allowed in kernel_launch)
__device__ float    g_xt[(size_t)N_ * SP * CIN];   // x -> [N, T*H*W, C]
__device__ uint32_t g_wfrag[KVOL * 2048];          // w -> [k][kk(4)][thread(128)][rr(4)]

__device__ __forceinline__ uint32_t f2tf32(float f) {
    uint32_t r; asm("cvt.rna.tf32.f32 %0, %1;" : "=r"(r) : "f"(f));
    return r;
}

// ---------------------------------------------------------------------------
// Merged prep: blocks [0,1568) transpose x; blocks [1568,1784) build w frags.
// ---------------------------------------------------------------------------
__global__ __launch_bounds__(256) void prep(const float* __restrict__ x,
                                            const float* __restrict__ w) {
    __shared__ float sm[32][33];
    int bx = blockIdx.x;
    if (bx < 1568) {
        int n  = bx >= 784 ? 1 : 0;
        int sb = bx - n * 784;
        int s0 = sb * 32;
        int tx = threadIdx.x & 31;
        int ty = threadIdx.x >> 5;
#pragma unroll
        for (int r = 0; r < 4; ++r) {
            int c = ty + r * 8;
            sm[c][tx] = x[((size_t)n * CIN + c) * SP + s0 + tx];
        }
        __syncthreads();
#pragma unroll
        for (int r = 0; r < 4; ++r) {
            int j = ty + r * 8;
            g_xt[((size_t)n * SP + s0 + j) * CIN + tx] = sm[tx][j];
        }
    } else {
        // fragment-ordered weights for mma.m16n8k8 (A row-major = [co][c]),
        // packed so one thread's 4 frag words per kk are contiguous (LDG.128).
        int i = (bx - 1568) * 256 + threadIdx.x;   // 0 .. 55295 = 27*2048
        int k  = i >> 11;
        int r  = i & 2047;
        int rr = r & 3;
        int t  = (r >> 2) & 127;   // c4*32 + lane
        int kk = r >> 9;
        int c4 = t >> 5;
        int ln = t & 31;
        int g  = ln >> 2, tg = ln & 3;
        int co = c4 * 16 + g + (rr & 1) * 8;
        int c  = kk * 8 + tg + (rr >> 1) * 4;
        g_wfrag[i] = f2tf32(w[((size_t)co * CIN + c) * KVOL + k]);
    }
}

// ---------------------------------------------------------------------------
// Compute one tap's 32 sampling records into smem (warp 0 only).
// Record = 8 corner weights + 8 pre-shifted indices, 16 words, 64 B.
// ---------------------------------------------------------------------------
__device__ __forceinline__ void make_rec(
    int k, int n, int s, float bt, float bh, float bw,
    const float* __restrict__ offset, float* __restrict__ rec /* [16] */)
{
    int kt = k / 9;
    int r9 = k - kt * 9;
    int kh = r9 / 3;
    int kw = r9 - kh * 3;

    const float* ob = offset + ((size_t)n * 81 + k * 3) * SP + s;   // coalesced in s
    float pt = bt + (float)kt + ob[0];
    float ph = bh + (float)kh + ob[SP];
    float pw = bw + (float)kw + ob[2 * (size_t)SP];

    float tf = floorf(pt), hf = floorf(ph), wf = floorf(pw);
    int t0 = (int)tf, h0 = (int)hf, w0 = (int)wf;
    float lt = pt - tf, lh = ph - hf, lw = pw - wf;

    float wt0 = (t0 >= 0 && t0 < T_)         ? 1.f - lt : 0.f;
    float wt1 = (t0 + 1 >= 0 && t0 + 1 < T_) ? lt       : 0.f;
    float wh0 = (h0 >= 0 && h0 < H_)         ? 1.f - lh : 0.f;
    float wh1 = (h0 + 1 >= 0 && h0 + 1 < H_) ? lh       : 0.f;
    float ww0 = (w0 >= 0 && w0 < W_)         ? 1.f - lw : 0.f;
    float ww1 = (w0 + 1 >= 0 && w0 + 1 < W_) ? lw       : 0.f;

    int t0c = min(max(t0, 0), T_ - 1), t1c = min(max(t0 + 1, 0), T_ - 1);
    int h0c = min(max(h0, 0), H_ - 1), h1c = min(max(h0 + 1, 0), H_ - 1);
    int w0c = min(max(w0, 0), W_ - 1), w1c = min(max(w0 + 1, 0), W_ - 1);

    int i00 = (t0c * H_ + h0c) * W_;
    int i01 = (t0c * H_ + h1c) * W_;
    int i10 = (t1c * H_ + h0c) * W_;
    int i11 = (t1c * H_ + h1c) * W_;

    float m00 = wt0 * wh0, m01 = wt0 * wh1, m10 = wt1 * wh0, m11 = wt1 * wh1;
    float4* rp = (float4*)rec;
    rp[0] = make_float4(m00 * ww0, m00 * ww1, m01 * ww0, m01 * ww1);
    rp[1] = make_float4(m10 * ww0, m10 * ww1, m11 * ww0, m11 * ww1);
    ((int4*)rp)[2] = make_int4((i00 + w0c) << 5, (i00 + w1c) << 5,
                               (i01 + w0c) << 5, (i01 + w1c) << 5);
    ((int4*)rp)[3] = make_int4((i10 + w0c) << 5, (i10 + w1c) << 5,
                               (i11 + w0c) << 5, (i11 + w1c) << 5);
}

// ---------------------------------------------------------------------------
// Gather one tap into col buffer using smem records.
// lane = channel; each warp handles 8 positions.
// ---------------------------------------------------------------------------
__device__ __forceinline__ void gather_tap(
    const float* __restrict__ rsm, const float* __restrict__ xb,
    int lane, int warpId, float* __restrict__ col)
{
    const float* b = xb + lane;
#pragma unroll
    for (int pp = 0; pp < 8; ++pp) {
        int q = warpId * 8 + pp;
        const float4* rp = (const float4*)(rsm + q * 16);
        float4 wa = rp[0];
        float4 wb = rp[1];
        int4   ia = ((const int4*)rp)[2];
        int4   ib = ((const int4*)rp)[3];
        float val;
        val  = wa.x * b[ia.x];
        val += wa.y * b[ia.y];
        val += wa.z * b[ia.z];
        val += wa.w * b[ia.w];
        val += wb.x * b[ib.x];
        val += wb.y * b[ib.y];
        val += wb.z * b[ib.z];
        val += wb.w * b[ib.w];
        col[q * CROW + lane] = __uint_as_float(f2tf32(val));
    }
}

// ---------------------------------------------------------------------------
// Main kernel: block = 32 positions x 64 couts, 128 threads, 9 blocks/SM.
// Pipeline, ONE barrier per tap: [rec(k+2) warp0 ; gather(k+1) ; mma(k)].
// ---------------------------------------------------------------------------
__global__ __launch_bounds__(128, 9) void deform_conv3d_main(
    const float* __restrict__ offset,
    const float* __restrict__ bias,
    float* __restrict__ out)
{
    __shared__ __align__(16) float col[2][32 * CROW];   // 9.2 KB
    __shared__ __align__(16) float rsm[2][32 * 16];     // 4 KB records

    const int nb  = blockIdx.x;          // 0 .. 1567
    const int n   = nb >= 784 ? 1 : 0;
    const int s0  = (nb - n * 784) * 32;
    const int tid = threadIdx.x;
    const int lane   = tid & 31;
    const int warpId = tid >> 5;         // 0..3

    const int g  = lane >> 2;
    const int tg = lane & 3;
    const int cobase = warpId * 16;

    // per-thread base coords for the rec path (warp 0: one position each)
    float bt = 0.f, bh = 0.f, bw = 0.f;
    int   sMine = s0 + tid;
    if (tid < 32) {
        int to = sMine / HW;
        int rem = sMine - to * HW;
        int ho = rem / W_;
        int wo = rem - ho * W_;
        bt = (float)(to - 1);
        bh = (float)(ho - 1);
        bw = (float)(wo - 1);
    }

    float d[4][4];
#pragma unroll
    for (int j = 0; j < 4; ++j)
#pragma unroll
        for (int i = 0; i < 4; ++i) d[j][i] = 0.f;

    const float* __restrict__ xb = g_xt + (size_t)n * SP * CIN;
    // per-thread base into frag-packed weights: [k][kk][t(128)][rr(4)]
    const uint32_t* __restrict__ wfrag = g_wfrag + (warpId * 32 + lane) * 4;

    // prologue
    if (tid < 32)
        make_rec(0, n, sMine, bt, bh, bw, offset, &rsm[0][tid * 16]);
    __syncthreads();
    gather_tap(rsm[0], xb, lane, warpId, col[0]);
    if (tid < 32)
        make_rec(1, n, sMine, bt, bh, bw, offset, &rsm[1][tid * 16]);
    __syncthreads();

#pragma unroll 1
    for (int k = 0; k < KVOL; ++k) {
        const int cur = k & 1;
        const int nxt = cur ^ 1;

        if (k + 2 < KVOL && tid < 32)
            make_rec(k + 2, n, sMine, bt, bh, bw, offset, &rsm[cur][tid * 16]);

        if (k + 1 < KVOL)
            gather_tap(rsm[nxt], xb, lane, warpId, col[nxt]);

        // ---- mma tap k: 16 x m16n8k8.tf32 per warp (co band x 32 pos) ----
        {
            const float* cb = col[cur];
            const uint32_t* wf = wfrag + k * 2048;
#pragma unroll
            for (int kk = 0; kk < 4; ++kk) {
                uint4 a = *(const uint4*)(wf + kk * 512);   // one LDG.128
                const int cbk = kk * 8;
#pragma unroll
                for (int j = 0; j < 4; ++j) {
                    const float* cr = cb + (8 * j + g) * CROW + cbk + tg;
                    uint32_t b0 = *(const uint32_t*)(cr);
                    uint32_t b1 = *(const uint32_t*)(cr + 4);
                    asm("mma.sync.aligned.m16n8k8.row.col.f32.tf32.tf32.f32 "
                        "{%0,%1,%2,%3}, {%4,%5,%6,%7}, {%8,%9}, {%0,%1,%2,%3};"
                        : "+f"(d[j][0]), "+f"(d[j][1]), "+f"(d[j][2]), "+f"(d[j][3])
                        : "r"(a.x), "r"(a.y), "r"(a.z), "r"(a.w), "r"(b0), "r"(b1));
                }
            }
        }
        __syncthreads();
    }

    // ---- epilogue: add bias, float2 stores ----
    float bg  = bias[cobase + g];
    float bg8 = bias[cobase + g + 8];
    float* ob0 = out + ((size_t)n * COUT + cobase + g)     * SP + s0 + 2 * tg;
    float* ob1 = out + ((size_t)n * COUT + cobase + g + 8) * SP + s0 + 2 * tg;
#pragma unroll
    for (int j = 0; j < 4; ++j) {
        *(float2*)(ob0 + 8 * j) = make_float2(d[j][0] + bg,  d[j][1] + bg);
        *(float2*)(ob1 + 8 * j) = make_float2(d[j][2] + bg8, d[j][3] + bg8);
    }
}

// ---------------------------------------------------------------------------
extern "C" void kernel_launch(void* const* d_in, const int* in_sizes, int n_in,
                              void* d_out, int out_size) {
    const float* x      = (const float*)d_in[0];
    const float* offset = (const float*)d_in[1];
    const float* weight = (const float*)d_in[2];
    const float* bias   = (const float*)d_in[3];
    float* out = (float*)d_out;

    prep<<<1784, 256>>>(x, weight);

    deform_conv3d_main<<<1568, 128>>>(offset, bias, out);
}

// round 15
// speedup vs baseline: 1.2233x; 1.0767x over previous
#include <cuda_runtime.h>
#include <cstdint>

#define N_    2
#define CIN   32
#define T_    8
#define H_    56
#define W_    56
#define COUT  64
#define KVOL  27
#define SP    25088   // T*H*W
#define HW    3136    // H*W
#define CROW  36      // col row stride: [pos][c], padded 32->36 (B-frag conflict-free)

// Scratch (no allocations allowed in kernel_launch)
__device__ float    g_xt[(size_t)N_ * SP * CIN];   // x -> [N, T*H*W, C]
__device__ uint32_t g_wfrag[KVOL * 2048];          // w -> [k][fragword(16)][c4*32+lane], tf32

__device__ __forceinline__ uint32_t f2tf32(float f) {
    uint32_t r; asm("cvt.rna.tf32.f32 %0, %1;" : "=r"(r) : "f"(f));
    return r;
}

// ---------------------------------------------------------------------------
// Merged prep: blocks [0,1568) transpose x; blocks [1568,1784) build w frags.
// ---------------------------------------------------------------------------
__global__ __launch_bounds__(256) void prep(const float* __restrict__ x,
                                            const float* __restrict__ w) {
    __shared__ float sm[32][33];
    int bx = blockIdx.x;
    if (bx < 1568) {
        int n  = bx >= 784 ? 1 : 0;
        int sb = bx - n * 784;
        int s0 = sb * 32;
        int tx = threadIdx.x & 31;
        int ty = threadIdx.x >> 5;
#pragma unroll
        for (int r = 0; r < 4; ++r) {
            int c = ty + r * 8;
            sm[c][tx] = x[((size_t)n * CIN + c) * SP + s0 + tx];
        }
        __syncthreads();
#pragma unroll
        for (int r = 0; r < 4; ++r) {
            int j = ty + r * 8;
            g_xt[((size_t)n * SP + s0 + j) * CIN + tx] = sm[tx][j];
        }
    } else {
        // fragment-ordered weights for mma.m16n8k8 (A row-major = [co][c])
        int i = (bx - 1568) * 256 + threadIdx.x;   // 0 .. 55295 = 27*2048
        int k  = i >> 11;
        int r  = i & 2047;
        int wd = r >> 7;
        int t  = r & 127;
        int c4 = t >> 5;
        int ln = t & 31;
        int g  = ln >> 2, tg = ln & 3;
        int kk = wd >> 2, rr = wd & 3;
        int co = c4 * 16 + g + (rr & 1) * 8;
        int c  = kk * 8 + tg + (rr >> 1) * 4;
        g_wfrag[i] = f2tf32(w[((size_t)co * CIN + c) * KVOL + k]);
    }
}

// ---------------------------------------------------------------------------
// Offset load for tap k (warp 0, one position per thread): 3 coalesced LDGs.
// ---------------------------------------------------------------------------
__device__ __forceinline__ float3 load_off(const float* __restrict__ offset,
                                           int n, int k, int s) {
    const float* ob = offset + ((size_t)n * 81 + k * 3) * SP + s;
    float3 o;
    o.x = ob[0];
    o.y = ob[SP];
    o.z = ob[2 * (size_t)SP];
    return o;
}

// ---------------------------------------------------------------------------
// Compute one tap's sampling record from pre-loaded offsets (registers).
// Record = 8 corner weights + 8 pre-shifted indices, 16 words, 64 B.
// ---------------------------------------------------------------------------
__device__ __forceinline__ void make_rec(
    int k, float bt, float bh, float bw, float3 off,
    float* __restrict__ rec /* [16] */)
{
    int kt = k / 9;
    int r9 = k - kt * 9;
    int kh = r9 / 3;
    int kw = r9 - kh * 3;

    float pt = bt + (float)kt + off.x;
    float ph = bh + (float)kh + off.y;
    float pw = bw + (float)kw + off.z;

    float tf = floorf(pt), hf = floorf(ph), wf = floorf(pw);
    int t0 = (int)tf, h0 = (int)hf, w0 = (int)wf;
    float lt = pt - tf, lh = ph - hf, lw = pw - wf;

    float wt0 = (t0 >= 0 && t0 < T_)         ? 1.f - lt : 0.f;
    float wt1 = (t0 + 1 >= 0 && t0 + 1 < T_) ? lt       : 0.f;
    float wh0 = (h0 >= 0 && h0 < H_)         ? 1.f - lh : 0.f;
    float wh1 = (h0 + 1 >= 0 && h0 + 1 < H_) ? lh       : 0.f;
    float ww0 = (w0 >= 0 && w0 < W_)         ? 1.f - lw : 0.f;
    float ww1 = (w0 + 1 >= 0 && w0 + 1 < W_) ? lw       : 0.f;

    int t0c = min(max(t0, 0), T_ - 1), t1c = min(max(t0 + 1, 0), T_ - 1);
    int h0c = min(max(h0, 0), H_ - 1), h1c = min(max(h0 + 1, 0), H_ - 1);
    int w0c = min(max(w0, 0), W_ - 1), w1c = min(max(w0 + 1, 0), W_ - 1);

    int i00 = (t0c * H_ + h0c) * W_;
    int i01 = (t0c * H_ + h1c) * W_;
    int i10 = (t1c * H_ + h0c) * W_;
    int i11 = (t1c * H_ + h1c) * W_;

    float m00 = wt0 * wh0, m01 = wt0 * wh1, m10 = wt1 * wh0, m11 = wt1 * wh1;
    float4* rp = (float4*)rec;
    rp[0] = make_float4(m00 * ww0, m00 * ww1, m01 * ww0, m01 * ww1);
    rp[1] = make_float4(m10 * ww0, m10 * ww1, m11 * ww0, m11 * ww1);
    ((int4*)rp)[2] = make_int4((i00 + w0c) << 5, (i00 + w1c) << 5,
                               (i01 + w0c) << 5, (i01 + w1c) << 5);
    ((int4*)rp)[3] = make_int4((i10 + w0c) << 5, (i10 + w1c) << 5,
                               (i11 + w0c) << 5, (i11 + w1c) << 5);
}

// ---------------------------------------------------------------------------
// Gather one tap into col buffer using smem records.
// lane = channel; each warp handles 8 positions.
// ---------------------------------------------------------------------------
__device__ __forceinline__ void gather_tap(
    const float* __restrict__ rsm, const float* __restrict__ xb,
    int lane, int warpId, float* __restrict__ col)
{
    const float* b = xb + lane;
#pragma unroll
    for (int pp = 0; pp < 8; ++pp) {
        int q = warpId * 8 + pp;
        const float4* rp = (const float4*)(rsm + q * 16);
        float4 wa = rp[0];
        float4 wb = rp[1];
        int4   ia = ((const int4*)rp)[2];
        int4   ib = ((const int4*)rp)[3];
        float val;
        val  = wa.x * b[ia.x];
        val += wa.y * b[ia.y];
        val += wa.z * b[ia.z];
        val += wa.w * b[ia.w];
        val += wb.x * b[ib.x];
        val += wb.y * b[ib.y];
        val += wb.z * b[ib.z];
        val += wb.w * b[ib.w];
        col[q * CROW + lane] = __uint_as_float(f2tf32(val));
    }
}

// ---------------------------------------------------------------------------
// Main kernel: block = 32 positions x 64 couts, 128 threads, 8 blocks/SM.
// Pipeline, ONE barrier per tap:
//   [rec(k+2) from prefetched regs + LDG off(k+3) ; gather(k+1) ; mma(k)]
// ---------------------------------------------------------------------------
__global__ __launch_bounds__(128, 8) void deform_conv3d_main(
    const float* __restrict__ offset,
    const float* __restrict__ bias,
    float* __restrict__ out)
{
    __shared__ __align__(16) float col[2][32 * CROW];   // 9.2 KB
    __shared__ __align__(16) float rsm[2][32 * 16];     // 4 KB records

    const int nb  = blockIdx.x;          // 0 .. 1567
    const int n   = nb >= 784 ? 1 : 0;
    const int s0  = (nb - n * 784) * 32;
    const int tid = threadIdx.x;
    const int lane   = tid & 31;
    const int warpId = tid >> 5;         // 0..3

    const int g  = lane >> 2;
    const int tg = lane & 3;
    const int cobase = warpId * 16;

    // per-thread base coords for the rec path (warp 0: one position each)
    float bt = 0.f, bh = 0.f, bw = 0.f;
    const int sMine = s0 + tid;
    if (tid < 32) {
        int to = sMine / HW;
        int rem = sMine - to * HW;
        int ho = rem / W_;
        int wo = rem - ho * W_;
        bt = (float)(to - 1);
        bh = (float)(ho - 1);
        bw = (float)(wo - 1);
    }

    float d[4][4];
#pragma unroll
    for (int j = 0; j < 4; ++j)
#pragma unroll
        for (int i = 0; i < 4; ++i) d[j][i] = 0.f;

    const float* __restrict__ xb = g_xt + (size_t)n * SP * CIN;
    const uint32_t* __restrict__ wfrag = g_wfrag + warpId * 32 + lane;

    // prologue: rec(0), rec(1); keep off(2) in flight in registers
    float3 offA = make_float3(0.f, 0.f, 0.f);
    if (tid < 32) {
        offA = load_off(offset, n, 0, sMine);
        make_rec(0, bt, bh, bw, offA, &rsm[0][tid * 16]);
        offA = load_off(offset, n, 1, sMine);
    }
    __syncthreads();
    gather_tap(rsm[0], xb, lane, warpId, col[0]);
    if (tid < 32) {
        make_rec(1, bt, bh, bw, offA, &rsm[1][tid * 16]);
        offA = load_off(offset, n, 2, sMine);
    }
    __syncthreads();

#pragma unroll 1
    for (int k = 0; k < KVOL; ++k) {
        const int cur = k & 1;
        const int nxt = cur ^ 1;

        // rec(k+2) from registers prefetched last interval; prefetch off(k+3)
        if (k + 2 < KVOL && tid < 32) {
            make_rec(k + 2, bt, bh, bw, offA, &rsm[cur][tid * 16]);
            if (k + 3 < KVOL)
                offA = load_off(offset, n, k + 3, sMine);
        }

        if (k + 1 < KVOL)
            gather_tap(rsm[nxt], xb, lane, warpId, col[nxt]);

        // ---- mma tap k: 16 x m16n8k8.tf32 per warp (co band x 32 pos) ----
        {
            const float* cb = col[cur];
            const uint32_t* wf = wfrag + k * 2048;
#pragma unroll
            for (int kk = 0; kk < 4; ++kk) {
                uint32_t a0 = wf[(kk * 4 + 0) * 128];
                uint32_t a1 = wf[(kk * 4 + 1) * 128];
                uint32_t a2 = wf[(kk * 4 + 2) * 128];
                uint32_t a3 = wf[(kk * 4 + 3) * 128];
                const int cbk = kk * 8;
#pragma unroll
                for (int j = 0; j < 4; ++j) {
                    const float* cr = cb + (8 * j + g) * CROW + cbk + tg;
                    uint32_t b0 = *(const uint32_t*)(cr);
                    uint32_t b1 = *(const uint32_t*)(cr + 4);
                    asm("mma.sync.aligned.m16n8k8.row.col.f32.tf32.tf32.f32 "
                        "{%0,%1,%2,%3}, {%4,%5,%6,%7}, {%8,%9}, {%0,%1,%2,%3};"
                        : "+f"(d[j][0]), "+f"(d[j][1]), "+f"(d[j][2]), "+f"(d[j][3])
                        : "r"(a0), "r"(a1), "r"(a2), "r"(a3), "r"(b0), "r"(b1));
                }
            }
        }
        __syncthreads();
    }

    // ---- epilogue: add bias, float2 stores ----
    float bg  = bias[cobase + g];
    float bg8 = bias[cobase + g + 8];
    float* ob0 = out + ((size_t)n * COUT + cobase + g)     * SP + s0 + 2 * tg;
    float* ob1 = out + ((size_t)n * COUT + cobase + g + 8) * SP + s0 + 2 * tg;
#pragma unroll
    for (int j = 0; j < 4; ++j) {
        *(float2*)(ob0 + 8 * j) = make_float2(d[j][0] + bg,  d[j][1] + bg);
        *(float2*)(ob1 + 8 * j) = make_float2(d[j][2] + bg8, d[j][3] + bg8);
    }
}

// ---------------------------------------------------------------------------
extern "C" void kernel_launch(void* const* d_in, const int* in_sizes, int n_in,
                              void* d_out, int out_size) {
    const float* x      = (const float*)d_in[0];
    const float* offset = (const float*)d_in[1];
    const float* weight = (const float*)d_in[2];
    const float* bias   = (const float*)d_in[3];
    float* out = (float*)d_out;

    prep<<<1784, 256>>>(x, weight);

    deform_conv3d_main<<<1568, 128>>>(offset, bias, out);
}